// round 5
// baseline (speedup 1.0000x reference)
#include <cuda_runtime.h>
#include <cuda_bf16.h>
#include <cstdint>

// ---------------------------------------------------------------------------
// SPN neuron: B=32768, F=512, P=256 scope pairs, M=8 mixture components.
//
// Log2-domain quadratic form per (p,m):
//   t_m = A1*x1^2 + B1*x1 + A2*x2^2 + B2*x2 + C     (scaled by log2 e)
//   lse2 = mx + log2( sum_m 2^(t_m - mx) )
//   out[b] = ln(2) * sum_p lse2_p
//
// R4: single kernel (coefficients computed in each block's prologue while the
// first cp.async chunk is in flight) + packed f32x2 math (FFMA2) so the M=8
// components ride in 4 register pairs: 32 FFMA -> 16 FFMA2, 8 FADD -> 4 ADD2.
// Double-buffered cp.async staging, persistent grid-stride blocks.
// ---------------------------------------------------------------------------

#define LOG2E_F    1.4426950408889634f
#define LN2_F      0.6931471805599453f
#define LOG2_2PI_F 2.6514961294723187f   // log2(2*pi)

constexpr int PF   = 512;   // features
constexpr int PP   = 256;   // scope pairs
constexpr int PM   = 8;     // mixture components
constexpr int ROWS = 8;     // batch rows per chunk

__device__ __forceinline__ float ex2f(float v) {
    float r; asm("ex2.approx.ftz.f32 %0, %1;" : "=f"(r) : "f"(v)); return r;
}
__device__ __forceinline__ float lg2f(float v) {
    float r; asm("lg2.approx.ftz.f32 %0, %1;" : "=f"(r) : "f"(v)); return r;
}
__device__ __forceinline__ void cp16(uint32_t smem_dst, const void* gmem_src) {
    asm volatile("cp.async.cg.shared.global [%0], [%1], 16;\n"
                 :: "r"(smem_dst), "l"(gmem_src));
}
__device__ __forceinline__ void cp_commit() {
    asm volatile("cp.async.commit_group;\n" ::: "memory");
}
template <int N>
__device__ __forceinline__ void cp_wait() {
    asm volatile("cp.async.wait_group %0;\n" :: "n"(N) : "memory");
}

// --- packed f32x2 helpers (Blackwell FFMA2/FADD2/FMUL2 via PTX) ------------
__device__ __forceinline__ unsigned long long pk2(float lo, float hi) {
    unsigned long long d;
    asm("mov.b64 %0, {%1, %2};" : "=l"(d) : "f"(lo), "f"(hi));
    return d;
}
__device__ __forceinline__ void upk2(float& lo, float& hi, unsigned long long v) {
    asm("mov.b64 {%0, %1}, %2;" : "=f"(lo), "=f"(hi) : "l"(v));
}
__device__ __forceinline__ unsigned long long fma2(unsigned long long a,
                                                   unsigned long long b,
                                                   unsigned long long c) {
    unsigned long long d;
    asm("fma.rn.f32x2 %0, %1, %2, %3;" : "=l"(d) : "l"(a), "l"(b), "l"(c));
    return d;
}
__device__ __forceinline__ unsigned long long add2(unsigned long long a,
                                                   unsigned long long b) {
    unsigned long long d;
    asm("add.rn.f32x2 %0, %1, %2;" : "=l"(d) : "l"(a), "l"(b));
    return d;
}
__device__ __forceinline__ unsigned long long mul2(unsigned long long a,
                                                   unsigned long long b) {
    unsigned long long d;
    asm("mul.rn.f32x2 %0, %1, %2;" : "=l"(d) : "l"(a), "l"(b));
    return d;
}

// ---------------------------------------------------------------------------
// Single kernel. blockDim = 256: thread == scope pair p.
//  Prologue: issue first cp.async chunk, then (overlapped with its flight)
//            detect scopes dtype and compute this thread's 8 component
//            coefficients from mean/std/weights, packed as 4 f32x2 pairs.
//  Main loop: persistent grid-stride over 8-row chunks, double-buffered
//            cp.async staging, packed quadratic + logsumexp, per-row
//            shuffle+smem reduction.
// ---------------------------------------------------------------------------
__global__ __launch_bounds__(256, 2)
void spn_main_kernel(const float* __restrict__ x,
                     const float* __restrict__ mean,
                     const float* __restrict__ stdv,
                     const float* __restrict__ wts,
                     const int*   __restrict__ w32,   // raw scopes as words
                     float* __restrict__ out,
                     int nchunks)
{
    __shared__ float sx[2][ROWS][PF];
    __shared__ float sred[8][ROWS];

    const int tid  = threadIdx.x;
    const int p    = tid;
    const int lane = tid & 31;
    const int warp = tid >> 5;

    const int stride = gridDim.x;
    const uint32_t sbase = (uint32_t)__cvta_generic_to_shared(&sx[0][0][0]);

    // ---- kick off first chunk's stage immediately ----
    int c = blockIdx.x;
    if (c < nchunks) {
        const char* src = (const char*)(x + (size_t)c * ROWS * PF);
        #pragma unroll
        for (int k = 0; k < 4; k++)
            cp16(sbase + (tid + k * 256) * 16, src + (tid + k * 256) * 16);
    }
    cp_commit();

    // ---- scopes dtype detection (parallel, one barrier) ----
    // int64 LE values in [0,512): every odd 32-bit word of the first 512 words
    // is zero. An int32 permutation of 0..511 has ~255 nonzero odd words.
    const int any_odd = __syncthreads_or(w32[2 * tid + 1] != 0);
    int s0, s1;
    if (any_odd) { s0 = w32[2 * p];     s1 = w32[2 * p + 1]; }   // int32
    else         { s0 = w32[4 * p];     s1 = w32[4 * p + 2]; }   // int64
    s0 &= (PF - 1);  s1 &= (PF - 1);

    // ---- per-thread coefficient computation (log2 domain) ----
    float A1[PM], B1[PM], A2[PM], B2[PM], Cc[PM];
    {
        float w[PM], wsum = 0.f;
        #pragma unroll
        for (int m = 0; m < PM; m++) { w[m] = wts[p * PM + m]; wsum += w[m]; }
        const float l2wsum = lg2f(wsum);
        #pragma unroll
        for (int m = 0; m < PM; m++) {
            int base = (p * PM + m) * 2;
            float mu1 = mean[base + 0], mu2 = mean[base + 1];
            float sd1 = stdv[base + 0], sd2 = stdv[base + 1];
            float i1 = 1.f / (sd1 * sd1);
            float i2 = 1.f / (sd2 * sd2);
            A1[m] = -0.5f * i1 * LOG2E_F;
            B1[m] =  mu1  * i1 * LOG2E_F;
            A2[m] = -0.5f * i2 * LOG2E_F;
            B2[m] =  mu2  * i2 * LOG2E_F;
            Cc[m] = -0.5f * LOG2E_F * (mu1 * mu1 * i1 + mu2 * mu2 * i2)
                    - lg2f(sd1) - lg2f(sd2) - LOG2_2PI_F
                    + lg2f(w[m]) - l2wsum;
        }
    }
    // Pack component pairs (m = 2q, 2q+1) into f32x2 registers.
    unsigned long long A1p[4], B1p[4], A2p[4], B2p[4], Cp[4];
    #pragma unroll
    for (int q = 0; q < 4; q++) {
        A1p[q] = pk2(A1[2 * q], A1[2 * q + 1]);
        B1p[q] = pk2(B1[2 * q], B1[2 * q + 1]);
        A2p[q] = pk2(A2[2 * q], A2[2 * q + 1]);
        B2p[q] = pk2(B2[2 * q], B2[2 * q + 1]);
        Cp [q] = pk2(Cc[2 * q], Cc[2 * q + 1]);
    }

    // ---- main loop ----
    int buf = 0;
    for (; c < nchunks; c += stride, buf ^= 1) {
        // Prefetch next chunk into the other buffer (empty group if none).
        int cn = c + stride;
        if (cn < nchunks) {
            const char* src = (const char*)(x + (size_t)cn * ROWS * PF);
            uint32_t dst = sbase + (uint32_t)(buf ^ 1) * (ROWS * PF * 4);
            #pragma unroll
            for (int k = 0; k < 4; k++)
                cp16(dst + (tid + k * 256) * 16, src + (tid + k * 256) * 16);
        }
        cp_commit();
        cp_wait<1>();          // current chunk's group has landed
        __syncthreads();       // visible to all; prev iter's sred consumed

        float acc[ROWS];
        #pragma unroll
        for (int r = 0; r < ROWS; r++) {
            float x1 = sx[buf][r][s0];
            float x2 = sx[buf][r][s1];
            // squares via one packed mul
            unsigned long long xp  = pk2(x1, x2);
            unsigned long long xsp = mul2(xp, xp);
            float x1s, x2s; upk2(x1s, x2s, xsp);

            unsigned long long x1b  = pk2(x1,  x1);
            unsigned long long x2b  = pk2(x2,  x2);
            unsigned long long x1sb = pk2(x1s, x1s);
            unsigned long long x2sb = pk2(x2s, x2s);

            // t = A1*x1s + B1*x1 + A2*x2s + B2*x2 + C   (4 FFMA2 per pair)
            float t[PM];
            unsigned long long tp[4];
            #pragma unroll
            for (int q = 0; q < 4; q++) {
                unsigned long long v = fma2(B2p[q], x2b, Cp[q]);
                v = fma2(A2p[q], x2sb, v);
                v = fma2(B1p[q], x1b, v);
                v = fma2(A1p[q], x1sb, v);
                tp[q] = v;
                upk2(t[2 * q], t[2 * q + 1], v);   // register aliasing: free
            }
            // max tree (depth 3)
            float m01 = fmaxf(t[0], t[1]), m23 = fmaxf(t[2], t[3]);
            float m45 = fmaxf(t[4], t[5]), m67 = fmaxf(t[6], t[7]);
            float mx  = fmaxf(fmaxf(m01, m23), fmaxf(m45, m67));

            // s = sum 2^(t - mx): 4 packed adds of -mx, 8 ex2, scalar add tree
            unsigned long long mxn = pk2(-mx, -mx);
            float e[PM];
            #pragma unroll
            for (int q = 0; q < 4; q++) {
                float u0, u1; upk2(u0, u1, add2(tp[q], mxn));
                e[2 * q]     = ex2f(u0);
                e[2 * q + 1] = ex2f(u1);
            }
            float s = ((e[0] + e[1]) + (e[2] + e[3]))
                    + ((e[4] + e[5]) + (e[6] + e[7]));
            acc[r] = mx + lg2f(s);
        }

        // Reduce 256 per-pair contributions -> 1 value per row
        #pragma unroll
        for (int r = 0; r < ROWS; r++) {
            float v = acc[r];
            #pragma unroll
            for (int off = 16; off; off >>= 1)
                v += __shfl_xor_sync(0xffffffffu, v, off);
            if (lane == 0) sred[warp][r] = v;
        }
        __syncthreads();

        if (tid < ROWS) {
            float s = 0.f;
            #pragma unroll
            for (int w = 0; w < 8; w++) s += sred[w][tid];
            out[c * ROWS + tid] = s * LN2_F;
        }
        // No trailing barrier: next iter's top barrier (after cp_wait) orders
        // this iter's sred reads against next iter's sred writes, and the
        // cp.async issued at next-iter top targets the buffer whose last
        // reads were sealed by this iteration's mid barrier.
    }
}

// ---------------------------------------------------------------------------
// Launch. Inputs: x f32[32768*512], mean f32[256*8*2], std f32[256*8*2],
// weights f32[256*8], scopes int{32,64}[512]. Output f32[32768].
// ---------------------------------------------------------------------------
extern "C" void kernel_launch(void* const* d_in, const int* in_sizes, int n_in,
                              void* d_out, int out_size)
{
    const float* x      = (const float*)d_in[0];
    const float* mean   = (const float*)d_in[1];
    const float* stdv   = (const float*)d_in[2];
    const float* wts    = (const float*)d_in[3];
    const int*   w32    = (const int*)d_in[4];
    float*       out    = (float*)d_out;

    const int B = in_sizes[0] / PF;          // 32768
    const int nchunks = B / ROWS;            // 4096

    int blocks = 1184;                       // 4 exact waves at 2 CTA/SM
    if (blocks > nchunks) blocks = nchunks;
    spn_main_kernel<<<blocks, 256>>>(x, mean, stdv, wts, w32, out, nchunks);
}

// round 6
// speedup vs baseline: 1.1497x; 1.1497x over previous
#include <cuda_runtime.h>
#include <cuda_bf16.h>
#include <cstdint>

// ---------------------------------------------------------------------------
// SPN neuron: B=32768, F=512, P=256 scope pairs, M=8 mixture components.
//
// Log2-domain quadratic form per (p,m):
//   t_m = A1*x1^2 + B1*x1 + A2*x2^2 + B2*x2 + C     (scaled by log2 e)
//   lse2 = mx + log2( sum_m 2^(t_m - mx) )
//   out[b] = ln(2) * sum_p lse2_p
//
// R5: single kernel. R3's proven scalar inner loop (FFMA chain; the R4 f32x2
// experiment spilled registers and regressed). Coefficients computed in each
// block's prologue; 296 persistent blocks (2 CTA/SM, full residency) so the
// prologue amortizes over ~14 chunks. Double-buffered cp.async staging.
// ---------------------------------------------------------------------------

#define LOG2E_F    1.4426950408889634f
#define LN2_F      0.6931471805599453f
#define LOG2_2PI_F 2.6514961294723187f   // log2(2*pi)

constexpr int PF   = 512;   // features
constexpr int PP   = 256;   // scope pairs
constexpr int PM   = 8;     // mixture components
constexpr int ROWS = 8;     // batch rows per chunk

__device__ __forceinline__ float ex2f(float v) {
    float r; asm("ex2.approx.ftz.f32 %0, %1;" : "=f"(r) : "f"(v)); return r;
}
__device__ __forceinline__ float lg2f(float v) {
    float r; asm("lg2.approx.ftz.f32 %0, %1;" : "=f"(r) : "f"(v)); return r;
}
__device__ __forceinline__ void cp16(uint32_t smem_dst, const void* gmem_src) {
    asm volatile("cp.async.cg.shared.global [%0], [%1], 16;\n"
                 :: "r"(smem_dst), "l"(gmem_src));
}
__device__ __forceinline__ void cp_commit() {
    asm volatile("cp.async.commit_group;\n" ::: "memory");
}
template <int N>
__device__ __forceinline__ void cp_wait() {
    asm volatile("cp.async.wait_group %0;\n" :: "n"(N) : "memory");
}

// ---------------------------------------------------------------------------
// Single kernel. blockDim = 256: thread == scope pair p.
// ---------------------------------------------------------------------------
__global__ __launch_bounds__(256, 2)
void spn_main_kernel(const float* __restrict__ x,
                     const float* __restrict__ mean,
                     const float* __restrict__ stdv,
                     const float* __restrict__ wts,
                     const int*   __restrict__ w32,   // raw scopes as words
                     float* __restrict__ out,
                     int nchunks)
{
    __shared__ float sx[2][ROWS][PF];
    __shared__ float sred[8][ROWS];

    const int tid  = threadIdx.x;
    const int p    = tid;
    const int lane = tid & 31;
    const int warp = tid >> 5;

    const int stride = gridDim.x;
    const uint32_t sbase = (uint32_t)__cvta_generic_to_shared(&sx[0][0][0]);

    // ---- kick off first chunk's stage immediately (overlaps prologue) ----
    int c = blockIdx.x;
    if (c < nchunks) {
        const char* src = (const char*)(x + (size_t)c * ROWS * PF);
        #pragma unroll
        for (int k = 0; k < 4; k++)
            cp16(sbase + (tid + k * 256) * 16, src + (tid + k * 256) * 16);
    }
    cp_commit();

    // ---- scopes dtype detection (parallel, one barrier) ----
    // int64 LE values in [0,512): every odd 32-bit word of the first 512
    // words is zero. An int32 permutation of 0..511 has ~255 nonzero odd
    // words. Reads stay within the first 512 words -> safe for both dtypes.
    const int any_odd = __syncthreads_or(w32[2 * tid + 1] != 0);
    int s0, s1;
    if (any_odd) { s0 = w32[2 * p]; s1 = w32[2 * p + 1]; }   // int32
    else         { s0 = w32[4 * p]; s1 = w32[4 * p + 2]; }   // int64
    s0 &= (PF - 1);  s1 &= (PF - 1);

    // ---- per-thread coefficient computation (log2 domain, prologue-only) ----
    float A1[PM], B1[PM], A2[PM], B2[PM], Cc[PM];
    {
        float w[PM], wsum = 0.f;
        #pragma unroll
        for (int m = 0; m < PM; m++) { w[m] = wts[p * PM + m]; wsum += w[m]; }
        const float l2wsum = lg2f(wsum);
        #pragma unroll
        for (int m = 0; m < PM; m++) {
            int base = (p * PM + m) * 2;
            float mu1 = mean[base + 0], mu2 = mean[base + 1];
            float sd1 = stdv[base + 0], sd2 = stdv[base + 1];
            float i1 = 1.f / (sd1 * sd1);
            float i2 = 1.f / (sd2 * sd2);
            A1[m] = -0.5f * i1 * LOG2E_F;
            B1[m] =  mu1  * i1 * LOG2E_F;
            A2[m] = -0.5f * i2 * LOG2E_F;
            B2[m] =  mu2  * i2 * LOG2E_F;
            Cc[m] = -0.5f * LOG2E_F * (mu1 * mu1 * i1 + mu2 * mu2 * i2)
                    - lg2f(sd1) - lg2f(sd2) - LOG2_2PI_F
                    + lg2f(w[m]) - l2wsum;
        }
    }

    // ---- main loop: double-buffered cp.async, R3 scalar math ----
    int buf = 0;
    for (; c < nchunks; c += stride, buf ^= 1) {
        int cn = c + stride;
        if (cn < nchunks) {
            const char* src = (const char*)(x + (size_t)cn * ROWS * PF);
            uint32_t dst = sbase + (uint32_t)(buf ^ 1) * (ROWS * PF * 4);
            #pragma unroll
            for (int k = 0; k < 4; k++)
                cp16(dst + (tid + k * 256) * 16, src + (tid + k * 256) * 16);
        }
        cp_commit();
        cp_wait<1>();          // current chunk's group has landed
        __syncthreads();       // visible to all; prev iter's sred consumed

        float acc[ROWS];
        #pragma unroll
        for (int r = 0; r < ROWS; r++) {
            float x1 = sx[buf][r][s0];
            float x2 = sx[buf][r][s1];
            float x1s = x1 * x1;
            float x2s = x2 * x2;

            float t[PM];
            #pragma unroll
            for (int m = 0; m < PM; m++) {
                float v = fmaf(B2[m], x2, Cc[m]);
                v = fmaf(A2[m], x2s, v);
                v = fmaf(B1[m], x1, v);
                v = fmaf(A1[m], x1s, v);
                t[m] = v;
            }
            float m01 = fmaxf(t[0], t[1]), m23 = fmaxf(t[2], t[3]);
            float m45 = fmaxf(t[4], t[5]), m67 = fmaxf(t[6], t[7]);
            float mx  = fmaxf(fmaxf(m01, m23), fmaxf(m45, m67));
            float s = 0.f;
            #pragma unroll
            for (int m = 0; m < PM; m++) s += ex2f(t[m] - mx);
            acc[r] = mx + lg2f(s);
        }

        // Reduce 256 per-pair contributions -> 1 value per row
        #pragma unroll
        for (int r = 0; r < ROWS; r++) {
            float v = acc[r];
            #pragma unroll
            for (int off = 16; off; off >>= 1)
                v += __shfl_xor_sync(0xffffffffu, v, off);
            if (lane == 0) sred[warp][r] = v;
        }
        __syncthreads();

        if (tid < ROWS) {
            float s = 0.f;
            #pragma unroll
            for (int w = 0; w < 8; w++) s += sred[w][tid];
            out[c * ROWS + tid] = s * LN2_F;
        }
        // No trailing barrier: next iter's top barrier (after cp_wait) orders
        // this iter's sred reads against next iter's sred writes, and the
        // cp.async issued at next-iter top targets the buffer whose last
        // reads were sealed by this iteration's mid barrier.
    }
}

// ---------------------------------------------------------------------------
// Launch. Inputs: x f32[32768*512], mean f32[256*8*2], std f32[256*8*2],
// weights f32[256*8], scopes int{32,64}[512]. Output f32[32768].
// ---------------------------------------------------------------------------
extern "C" void kernel_launch(void* const* d_in, const int* in_sizes, int n_in,
                              void* d_out, int out_size)
{
    const float* x      = (const float*)d_in[0];
    const float* mean   = (const float*)d_in[1];
    const float* stdv   = (const float*)d_in[2];
    const float* wts    = (const float*)d_in[3];
    const int*   w32    = (const int*)d_in[4];
    float*       out    = (float*)d_out;

    const int B = in_sizes[0] / PF;          // 32768
    const int nchunks = B / ROWS;            // 4096

    // 296 = 148 SMs x 2 CTAs: one fully-resident persistent wave.
    int blocks = 296;
    if (blocks > nchunks) blocks = nchunks;
    spn_main_kernel<<<blocks, 256>>>(x, mean, stdv, wts, w32, out, nchunks);
}

// round 7
// speedup vs baseline: 1.2025x; 1.0460x over previous
#include <cuda_runtime.h>
#include <cuda_bf16.h>
#include <cstdint>

// ---------------------------------------------------------------------------
// SPN neuron: B=32768, F=512, P=256 scope pairs, M=8 mixture components.
//
// Log2-domain quadratic form per (p,m):
//   t_m = A1*x1^2 + B1*x1 + A2*x2^2 + B2*x2 + C     (scaled by log2 e)
//   lse2 = mx + log2( sum_m 2^(t_m - mx) )
//   out[b] = ln(2) * sum_p lse2_p
//
// R6: R5 structure + occupancy push: __launch_bounds__(256, 3) caps regs at
// 85 -> 3 CTAs/SM (24 warps), grid = 444 persistent blocks (148 SM x 3).
// The kernel is ~2x above its ~20us issue floor purely from latency exposure
// at 16 warps/SM; +50% warps should close most of that gap.
// ---------------------------------------------------------------------------

#define LOG2E_F    1.4426950408889634f
#define LN2_F      0.6931471805599453f
#define LOG2_2PI_F 2.6514961294723187f   // log2(2*pi)

constexpr int PF   = 512;   // features
constexpr int PP   = 256;   // scope pairs
constexpr int PM   = 8;     // mixture components
constexpr int ROWS = 8;     // batch rows per chunk

__device__ __forceinline__ float ex2f(float v) {
    float r; asm("ex2.approx.ftz.f32 %0, %1;" : "=f"(r) : "f"(v)); return r;
}
__device__ __forceinline__ float lg2f(float v) {
    float r; asm("lg2.approx.ftz.f32 %0, %1;" : "=f"(r) : "f"(v)); return r;
}
__device__ __forceinline__ void cp16(uint32_t smem_dst, const void* gmem_src) {
    asm volatile("cp.async.cg.shared.global [%0], [%1], 16;\n"
                 :: "r"(smem_dst), "l"(gmem_src));
}
__device__ __forceinline__ void cp_commit() {
    asm volatile("cp.async.commit_group;\n" ::: "memory");
}
template <int N>
__device__ __forceinline__ void cp_wait() {
    asm volatile("cp.async.wait_group %0;\n" :: "n"(N) : "memory");
}

// ---------------------------------------------------------------------------
// Single kernel. blockDim = 256: thread == scope pair p.
// ---------------------------------------------------------------------------
__global__ __launch_bounds__(256, 3)
void spn_main_kernel(const float* __restrict__ x,
                     const float* __restrict__ mean,
                     const float* __restrict__ stdv,
                     const float* __restrict__ wts,
                     const int*   __restrict__ w32,   // raw scopes as words
                     float* __restrict__ out,
                     int nchunks)
{
    __shared__ float sx[2][ROWS][PF];
    __shared__ float sred[8][ROWS];

    const int tid  = threadIdx.x;
    const int p    = tid;
    const int lane = tid & 31;
    const int warp = tid >> 5;

    const int stride = gridDim.x;
    const uint32_t sbase = (uint32_t)__cvta_generic_to_shared(&sx[0][0][0]);

    // ---- kick off first chunk's stage immediately (overlaps prologue) ----
    int c = blockIdx.x;
    if (c < nchunks) {
        const char* src = (const char*)(x + (size_t)c * ROWS * PF);
        #pragma unroll
        for (int k = 0; k < 4; k++)
            cp16(sbase + (tid + k * 256) * 16, src + (tid + k * 256) * 16);
    }
    cp_commit();

    // ---- scopes dtype detection (parallel, one barrier) ----
    // int64 LE values in [0,512): every odd 32-bit word of the first 512
    // words is zero. An int32 permutation of 0..511 has ~255 nonzero odd
    // words. Reads stay within the first 512 words -> safe for both dtypes.
    const int any_odd = __syncthreads_or(w32[2 * tid + 1] != 0);
    int s0, s1;
    if (any_odd) { s0 = w32[2 * p]; s1 = w32[2 * p + 1]; }   // int32
    else         { s0 = w32[4 * p]; s1 = w32[4 * p + 2]; }   // int64
    s0 &= (PF - 1);  s1 &= (PF - 1);

    // ---- per-thread coefficient computation (log2 domain, prologue-only) ----
    float A1[PM], B1[PM], A2[PM], B2[PM], Cc[PM];
    {
        float w[PM], wsum = 0.f;
        #pragma unroll
        for (int m = 0; m < PM; m++) { w[m] = wts[p * PM + m]; wsum += w[m]; }
        const float l2wsum = lg2f(wsum);
        #pragma unroll
        for (int m = 0; m < PM; m++) {
            int base = (p * PM + m) * 2;
            float mu1 = mean[base + 0], mu2 = mean[base + 1];
            float sd1 = stdv[base + 0], sd2 = stdv[base + 1];
            float i1 = 1.f / (sd1 * sd1);
            float i2 = 1.f / (sd2 * sd2);
            A1[m] = -0.5f * i1 * LOG2E_F;
            B1[m] =  mu1  * i1 * LOG2E_F;
            A2[m] = -0.5f * i2 * LOG2E_F;
            B2[m] =  mu2  * i2 * LOG2E_F;
            Cc[m] = -0.5f * LOG2E_F * (mu1 * mu1 * i1 + mu2 * mu2 * i2)
                    - lg2f(sd1) - lg2f(sd2) - LOG2_2PI_F
                    + lg2f(w[m]) - l2wsum;
        }
    }

    // ---- main loop: double-buffered cp.async, scalar math ----
    int buf = 0;
    for (; c < nchunks; c += stride, buf ^= 1) {
        int cn = c + stride;
        if (cn < nchunks) {
            const char* src = (const char*)(x + (size_t)cn * ROWS * PF);
            uint32_t dst = sbase + (uint32_t)(buf ^ 1) * (ROWS * PF * 4);
            #pragma unroll
            for (int k = 0; k < 4; k++)
                cp16(dst + (tid + k * 256) * 16, src + (tid + k * 256) * 16);
        }
        cp_commit();
        cp_wait<1>();          // current chunk's group has landed
        __syncthreads();       // visible to all; prev iter's sred consumed

        float acc[ROWS];
        #pragma unroll
        for (int r = 0; r < ROWS; r++) {
            float x1 = sx[buf][r][s0];
            float x2 = sx[buf][r][s1];
            float x1s = x1 * x1;
            float x2s = x2 * x2;

            float t[PM];
            #pragma unroll
            for (int m = 0; m < PM; m++) {
                float v = fmaf(B2[m], x2, Cc[m]);
                v = fmaf(A2[m], x2s, v);
                v = fmaf(B1[m], x1, v);
                v = fmaf(A1[m], x1s, v);
                t[m] = v;
            }
            float m01 = fmaxf(t[0], t[1]), m23 = fmaxf(t[2], t[3]);
            float m45 = fmaxf(t[4], t[5]), m67 = fmaxf(t[6], t[7]);
            float mx  = fmaxf(fmaxf(m01, m23), fmaxf(m45, m67));
            // ex2 in place (no extra e[] array; keeps live state small)
            #pragma unroll
            for (int m = 0; m < PM; m++) t[m] = ex2f(t[m] - mx);
            float s = ((t[0] + t[1]) + (t[2] + t[3]))
                    + ((t[4] + t[5]) + (t[6] + t[7]));
            acc[r] = mx + lg2f(s);
        }

        // Reduce 256 per-pair contributions -> 1 value per row
        #pragma unroll
        for (int r = 0; r < ROWS; r++) {
            float v = acc[r];
            #pragma unroll
            for (int off = 16; off; off >>= 1)
                v += __shfl_xor_sync(0xffffffffu, v, off);
            if (lane == 0) sred[warp][r] = v;
        }
        __syncthreads();

        if (tid < ROWS) {
            float s = 0.f;
            #pragma unroll
            for (int w = 0; w < 8; w++) s += sred[w][tid];
            out[c * ROWS + tid] = s * LN2_F;
        }
        // No trailing barrier: next iter's top barrier (after cp_wait) orders
        // this iter's sred reads against next iter's sred writes, and the
        // cp.async issued at next-iter top targets the buffer whose last
        // reads were sealed by this iteration's mid barrier.
    }
}

// ---------------------------------------------------------------------------
// Launch. Inputs: x f32[32768*512], mean f32[256*8*2], std f32[256*8*2],
// weights f32[256*8], scopes int{32,64}[512]. Output f32[32768].
// ---------------------------------------------------------------------------
extern "C" void kernel_launch(void* const* d_in, const int* in_sizes, int n_in,
                              void* d_out, int out_size)
{
    const float* x      = (const float*)d_in[0];
    const float* mean   = (const float*)d_in[1];
    const float* stdv   = (const float*)d_in[2];
    const float* wts    = (const float*)d_in[3];
    const int*   w32    = (const int*)d_in[4];
    float*       out    = (float*)d_out;

    const int B = in_sizes[0] / PF;          // 32768
    const int nchunks = B / ROWS;            // 4096

    // 444 = 148 SMs x 3 CTAs: one fully-resident persistent wave.
    int blocks = 444;
    if (blocks > nchunks) blocks = nchunks;
    spn_main_kernel<<<blocks, 256>>>(x, mean, stdv, wts, w32, out, nchunks);
}